// round 16
// baseline (speedup 1.0000x reference)
#include <cuda_runtime.h>
#include <cuda_fp16.h>
#include <math.h>
#include <cstdint>

// Shapes: B=64, N=1024, F=4, H=128. BN = 65536 nodes.
// Output: pi [64,1024] then v [64,1] -> 65600 floats.
#define BN 65536
#define NT32 2048          // 32-node tiles
#define GRID_LOGITS 256    // x4 warps = 1024 -> exactly 2 tiles/warp

typedef unsigned long long ull;

__device__ float g_hx[128];
__device__ uint4 g_wah[2048];   // W_attn as permuted half2, [128][64] dense

// ---------------- scalar helpers ----------------
__device__ __forceinline__ float tanh_fast(float x) {
    float r; asm("tanh.approx.f32 %0, %1;" : "=f"(r) : "f"(x)); return r;
}
// ---------------- packed f32x2 helpers ----------------
__device__ __forceinline__ ull pack2(float lo, float hi) {
    ull r; asm("mov.b64 %0, {%1, %2};" : "=l"(r) : "f"(lo), "f"(hi)); return r;
}
__device__ __forceinline__ void unpack2(ull p, float& lo, float& hi) {
    asm("mov.b64 {%0, %1}, %2;" : "=f"(lo), "=f"(hi) : "l"(p));
}
__device__ __forceinline__ ull fma2(ull a, ull b, ull c) {
    ull r; asm("fma.rn.f32x2 %0, %1, %2, %3;" : "=l"(r) : "l"(a), "l"(b), "l"(c)); return r;
}
__device__ __forceinline__ ull mul2(ull a, ull b) {
    ull r; asm("mul.rn.f32x2 %0, %1, %2;" : "=l"(r) : "l"(a), "l"(b)); return r;
}
__device__ __forceinline__ ull add2(ull a, ull b) {
    ull r; asm("add.rn.f32x2 %0, %1, %2;" : "=l"(r) : "l"(a), "l"(b)); return r;
}
// packed relu(fp32x2) -> half2 bits
__device__ __forceinline__ unsigned relu_h2(ull e, __half2 hz) {
    float lo, hi;
    unpack2(e, lo, hi);
    __half2 h = __hmax2(__floats2half2_rn(lo, hi), hz);
    return *reinterpret_cast<unsigned*>(&h);
}

// ---------------------------------------------------------------------------
// Kernel 0: fused gates + hx + W_attn->half2 pre-conversion.
// 32 blocks x 128 threads; one warp per h index for the gates.
// ---------------------------------------------------------------------------
__global__ void k_gh(const float* __restrict__ Wih, const float* __restrict__ bih,
                     const float* __restrict__ bhh, const float* __restrict__ q,
                     const float* __restrict__ Wattn) {
    int t = threadIdx.x;
    int lane = t & 31, wid = t >> 5;

    // ---- W_attn conversion: 4096 threads x one float4 each ----
    {
        __half2* gw2 = (__half2*)g_wah;
        int i = (blockIdx.x * 128 + t) * 4;
        float4 wv = __ldg((const float4*)(Wattn + i));
        int h = i >> 7, k = i & 127;
        int k2 = k >> 1;
        int kb8 = k2 & ~7, j = k2 & 7;       // j in {0,2,4,6}
        int c1 = kb8 + ((j < 4) ? 2 * j : 2 * j - 7);
        gw2[h * 64 + c1]     = __floats2half2_rn(wv.x, wv.y);
        gw2[h * 64 + c1 + 2] = __floats2half2_rn(wv.z, wv.w);
    }

    // ---- gates i, g, o for h = blockIdx*4 + wid (f*c0 = 0) ----
    int h = blockIdx.x * 4 + wid;
    float4 qv = __ldg((const float4*)q + lane);
    int rows[3] = {h, 256 + h, 384 + h};
    float acc[3];
    #pragma unroll
    for (int i = 0; i < 3; i++) {
        float4 wv = __ldg((const float4*)(Wih + rows[i] * 128) + lane);
        acc[i] = wv.x * qv.x + wv.y * qv.y + wv.z * qv.z + wv.w * qv.w;
    }
    #pragma unroll
    for (int o = 16; o > 0; o >>= 1)
        #pragma unroll
        for (int i = 0; i < 3; i++)
            acc[i] += __shfl_xor_sync(0xffffffff, acc[i], o);

    if (lane == 0) {
        float ig = acc[0] + bih[h] + bhh[h];
        float gg = acc[1] + bih[256 + h] + bhh[256 + h];
        float og = acc[2] + bih[384 + h] + bhh[384 + h];
        float si = 1.f / (1.f + __expf(-ig));
        float so = 1.f / (1.f + __expf(-og));
        float cx = si * tanh_fast(gg);
        g_hx[h] = so * tanh_fast(cx);
    }
}

// ---------------------------------------------------------------------------
// Kernel 1: logits, warp-autonomous 32n x 128h tiles; embedding fused into the
// GEMM k-loop (B fragments in registers); A staged from pre-converted half2
// buffer (16 LDG.128 + 16 STS.128 per thread); both tiles' node features
// hoisted to kernel start -> tile loop is barrier-free.
// ---------------------------------------------------------------------------
#define AH_STRIDE 72
#define AS_OFF   0        // 128*72 half2 = 9216 float-slots
#define XS_OFF   9216     // 4 warps x 64 float4 = 1024 floats (2 tiles)
#define WPS_OFF  10240    // 64 k2 x 4 ull = 512 floats
#define BPS_OFF  10752    // 64 ull = 128 floats
#define HXS_OFF  10880    // 128
#define VPS_OFF  11008    // 128
#define SM_FLOATS 11136   // 44.5 KB/CTA, x2 = 89 KB

__global__ __launch_bounds__(128, 2)
void k_logits(const float* __restrict__ nf, const float* __restrict__ Wemb,
              const float* __restrict__ bemb, const float* __restrict__ vparam,
              float* __restrict__ out) {
    extern __shared__ float sm[];
    __half2* as2 = (__half2*)sm;              // [128][72]
    ull* wps     = (ull*)(sm + WPS_OFF);      // [64][4]
    ull* bps     = (ull*)(sm + BPS_OFF);      // [64]
    float* hxs   = sm + HXS_OFF;
    float* vps   = sm + VPS_OFF;

    int t = threadIdx.x;
    int lane = t & 31, w = t >> 5;
    int g = lane >> 2, tc = lane & 3;

    float4* xsw = (float4*)(sm + XS_OFF) + w * 64;

    // ---- A staging from pre-converted buffer: 16 uint4 per thread ----
    #pragma unroll
    for (int it = 0; it < 16; it++) {
        int i = t + it * 128;
        int row = i >> 4, seg = i & 15;     // 16 uint4 per 64-half2 row
        *(uint4*)(as2 + row * AH_STRIDE + seg * 4) = g_wah[i];
    }
    // packed W_emb / b_emb: pair rows (2k2, 2k2+1)
    if (t < 64) {
        int k2 = t;
        #pragma unroll
        for (int f = 0; f < 4; f++)
            wps[k2 * 4 + f] = pack2(Wemb[(2 * k2) * 4 + f],
                                    Wemb[(2 * k2 + 1) * 4 + f]);
        bps[k2] = pack2(bemb[2 * k2], bemb[2 * k2 + 1]);
    }
    hxs[t] = g_hx[t];
    vps[t] = vparam[t];

    const ull C3 = pack2(-0.3333333333f, -0.3333333333f);
    const ull C5 = pack2(0.1333333333f, 0.1333333333f);
    const ull C7 = pack2(-0.0539682540f, -0.0539682540f);
    const __half2 hzero = __floats2half2_rn(0.f, 0.f);

    // ---- hoist BOTH tiles' node features (tiles gw and gw+1024) ----
    int gw = blockIdx.x * 4 + w;       // global warp id: 0..1023
    xsw[lane]      = __ldg((const float4*)nf + (gw * 32 + lane));
    xsw[32 + lane] = __ldg((const float4*)nf + ((gw + 1024) * 32 + lane));

    __syncthreads();   // staging + xs complete (only sync in the kernel)

    #pragma unroll
    for (int it = 0; it < 2; it++) {
        int base = (gw + it * 1024) * 32;

        // lane's 4 nodes, packed
        ull xp[4][4];
        #pragma unroll
        for (int ni = 0; ni < 4; ni++) {
            float4 x = xsw[it * 32 + ni * 8 + g];
            xp[ni][0] = pack2(x.x, x.x);
            xp[ni][1] = pack2(x.y, x.y);
            xp[ni][2] = pack2(x.z, x.z);
            xp[ni][3] = pack2(x.w, x.w);
        }

        // ---- fused embed + fp16 GEMM: warp tile 128h x 32n ----
        float accr[8][4][4];
        #pragma unroll
        for (int mi = 0; mi < 8; mi++)
            #pragma unroll
            for (int ni = 0; ni < 4; ni++)
                #pragma unroll
                for (int j = 0; j < 4; j++) accr[mi][ni][j] = 0.f;

        #pragma unroll
        for (int kt = 0; kt < 8; kt++) {
            int k2a = kt * 8 + tc;
            int k2b = k2a + 4;
            ull wa0 = wps[k2a * 4], wa1 = wps[k2a * 4 + 1];
            ull wa2 = wps[k2a * 4 + 2], wa3 = wps[k2a * 4 + 3];
            ull ba = bps[k2a];
            ull wb0 = wps[k2b * 4], wb1 = wps[k2b * 4 + 1];
            ull wb2 = wps[k2b * 4 + 2], wb3 = wps[k2b * 4 + 3];
            ull bb = bps[k2b];

            uint2 bfr[4];
            #pragma unroll
            for (int ni = 0; ni < 4; ni++) {
                ull ea = ba;
                ea = fma2(xp[ni][0], wa0, ea);
                ea = fma2(xp[ni][1], wa1, ea);
                ea = fma2(xp[ni][2], wa2, ea);
                ea = fma2(xp[ni][3], wa3, ea);
                ull eb = bb;
                eb = fma2(xp[ni][0], wb0, eb);
                eb = fma2(xp[ni][1], wb1, eb);
                eb = fma2(xp[ni][2], wb2, eb);
                eb = fma2(xp[ni][3], wb3, eb);
                bfr[ni].x = relu_h2(ea, hzero);
                bfr[ni].y = relu_h2(eb, hzero);
            }

            int cb = kt * 8 + 2 * tc;
            #pragma unroll
            for (int mi = 0; mi < 8; mi++) {
                int r = mi * 16 + g;
                uint2 alo = *(const uint2*)(as2 + r * AH_STRIDE + cb);
                uint2 ahi = *(const uint2*)(as2 + (r + 8) * AH_STRIDE + cb);
                #pragma unroll
                for (int ni = 0; ni < 4; ni++) {
                    asm volatile(
                        "mma.sync.aligned.m16n8k16.row.col.f32.f16.f16.f32 "
                        "{%0,%1,%2,%3}, {%4,%5,%6,%7}, {%8,%9}, {%0,%1,%2,%3};"
                        : "+f"(accr[mi][ni][0]), "+f"(accr[mi][ni][1]),
                          "+f"(accr[mi][ni][2]), "+f"(accr[mi][ni][3])
                        : "r"(alo.x), "r"(ahi.x), "r"(alo.y), "r"(ahi.y),
                          "r"(bfr[ni].x), "r"(bfr[ni].y));
                }
            }
        }

        // ---- epilogue: v-weighted tanh, h-sum fully warp-internal ----
        ull s2[4];
        #pragma unroll
        for (int ni = 0; ni < 4; ni++) s2[ni] = pack2(0.f, 0.f);
        #pragma unroll
        for (int mi = 0; mi < 8; mi++) {
            int h0 = mi * 16 + g;
            ull hxa = pack2(hxs[h0], hxs[h0]);
            ull hxb = pack2(hxs[h0 + 8], hxs[h0 + 8]);
            ull va  = pack2(vps[h0], vps[h0]);
            ull vb  = pack2(vps[h0 + 8], vps[h0 + 8]);
            #pragma unroll
            for (int ni = 0; ni < 4; ni++) {
                ull ya = add2(pack2(accr[mi][ni][0], accr[mi][ni][1]), hxa);
                ull yb = add2(pack2(accr[mi][ni][2], accr[mi][ni][3]), hxb);
                if (mi < 4) {
                    float l0, l1;
                    unpack2(ya, l0, l1);
                    s2[ni] = fma2(va, pack2(tanh_fast(l0), tanh_fast(l1)), s2[ni]);
                    unpack2(yb, l0, l1);
                    s2[ni] = fma2(vb, pack2(tanh_fast(l0), tanh_fast(l1)), s2[ni]);
                } else {
                    ull ua = mul2(ya, ya);
                    ull qa = fma2(ua, C7, C5);
                    qa = fma2(ua, qa, C3);
                    ull ta = fma2(mul2(ya, ua), qa, ya);
                    s2[ni] = fma2(va, ta, s2[ni]);

                    ull ub = mul2(yb, yb);
                    ull qb = fma2(ub, C7, C5);
                    qb = fma2(ub, qb, C3);
                    ull tb = fma2(mul2(yb, ub), qb, yb);
                    s2[ni] = fma2(vb, tb, s2[ni]);
                }
            }
        }

        // reduce over g (lane bits 2..4)
        float pl[4][2];
        #pragma unroll
        for (int ni = 0; ni < 4; ni++) unpack2(s2[ni], pl[ni][0], pl[ni][1]);
        #pragma unroll
        for (int off = 4; off < 32; off <<= 1)
            #pragma unroll
            for (int ni = 0; ni < 4; ni++)
                #pragma unroll
                for (int j = 0; j < 2; j++)
                    pl[ni][j] += __shfl_xor_sync(0xffffffff, pl[ni][j], off);

        if (g == 0) {
            #pragma unroll
            for (int ni = 0; ni < 4; ni++)
                ((float2*)(out + base))[ni * 4 + tc] =
                    make_float2(pl[ni][0], pl[ni][1]);
        }
    }
}

// ---------------------------------------------------------------------------
// Kernel 2: softmax over N=1024 per batch (blocks 0..63) + v output (block 64).
// ---------------------------------------------------------------------------
__global__ void k_softmax(const float* __restrict__ Wval,
                          const float* __restrict__ bval,
                          float* __restrict__ out) {
    __shared__ float wred[8];
    __shared__ float bcast[2];
    int b = blockIdx.x;
    int t = threadIdx.x;
    int lane = t & 31, wid = t >> 5;

    if (b == 64) {
        if (wid == 0) {
            float s = g_hx[lane] * Wval[lane]
                    + g_hx[32 + lane] * Wval[32 + lane]
                    + g_hx[64 + lane] * Wval[64 + lane]
                    + g_hx[96 + lane] * Wval[96 + lane];
            #pragma unroll
            for (int o = 16; o > 0; o >>= 1)
                s += __shfl_xor_sync(0xffffffff, s, o);
            float v = s + bval[0];
            out[BN + lane] = v;
            out[BN + 32 + lane] = v;
        }
        return;
    }

    float* row = out + b * 1024;
    float4 x = ((const float4*)row)[t];
    float m = fmaxf(fmaxf(x.x, x.y), fmaxf(x.z, x.w));
    #pragma unroll
    for (int o = 16; o > 0; o >>= 1)
        m = fmaxf(m, __shfl_xor_sync(0xffffffff, m, o));
    if (lane == 0) wred[wid] = m;
    __syncthreads();
    if (wid == 0) {
        float mm = wred[lane & 7];
        #pragma unroll
        for (int o = 4; o > 0; o >>= 1)
            mm = fmaxf(mm, __shfl_xor_sync(0xffffffff, mm, o));
        if (lane == 0) bcast[0] = mm;
    }
    __syncthreads();
    float M = bcast[0];
    float e0 = __expf(x.x - M);
    float e1 = __expf(x.y - M);
    float e2 = __expf(x.z - M);
    float e3 = __expf(x.w - M);
    float s = e0 + e1 + e2 + e3;
    #pragma unroll
    for (int o = 16; o > 0; o >>= 1)
        s += __shfl_xor_sync(0xffffffff, s, o);
    if (lane == 0) wred[wid] = s;
    __syncthreads();
    if (wid == 0) {
        float ss = wred[lane & 7];
        #pragma unroll
        for (int o = 4; o > 0; o >>= 1)
            ss += __shfl_xor_sync(0xffffffff, ss, o);
        if (lane == 0) bcast[1] = ss;
    }
    __syncthreads();
    float inv = 1.f / bcast[1];
    float4 r;
    r.x = e0 * inv; r.y = e1 * inv; r.z = e2 * inv; r.w = e3 * inv;
    ((float4*)row)[t] = r;
}

// ---------------------------------------------------------------------------
extern "C" void kernel_launch(void* const* d_in, const int* in_sizes, int n_in,
                              void* d_out, int out_size) {
    const float* nf     = (const float*)d_in[0];
    const float* Wemb   = (const float*)d_in[2];
    const float* bemb   = (const float*)d_in[3];
    const float* Wih    = (const float*)d_in[4];
    const float* bih    = (const float*)d_in[5];
    const float* bhh    = (const float*)d_in[7];
    const float* query  = (const float*)d_in[8];
    const float* Wattn  = (const float*)d_in[9];
    const float* vparam = (const float*)d_in[10];
    const float* Wval   = (const float*)d_in[11];
    const float* bval   = (const float*)d_in[12];
    float* out = (float*)d_out;

    static int smem_set = 0;
    const int smem_bytes = SM_FLOATS * 4;
    if (!smem_set) {
        cudaFuncSetAttribute(k_logits, cudaFuncAttributeMaxDynamicSharedMemorySize,
                             smem_bytes);
        smem_set = 1;
    }

    k_gh<<<32, 128>>>(Wih, bih, bhh, query, Wattn);
    k_logits<<<GRID_LOGITS, 128, smem_bytes>>>(nf, Wemb, bemb, vparam, out);
    k_softmax<<<65, 256>>>(Wval, bval, out);
}

// round 17
// speedup vs baseline: 1.0034x; 1.0034x over previous
#include <cuda_runtime.h>
#include <cuda_fp16.h>
#include <math.h>
#include <cstdint>

// Shapes: B=64, N=1024, F=4, H=128. BN = 65536 nodes.
// Output: pi [64,1024] then v [64,1] -> 65600 floats.
#define BN 65536
#define GRID_LOGITS 256    // x4 warps = 1024 warp-tiles -> exactly 2 tiles/warp

typedef unsigned long long ull;

__device__ float g_hx[128];
__device__ int g_cnt;      // gate-completion warp counter (reset by k_softmax)

// ---------------- scalar helpers ----------------
__device__ __forceinline__ float tanh_fast(float x) {
    float r; asm("tanh.approx.f32 %0, %1;" : "=f"(r) : "f"(x)); return r;
}
// ---------------- packed f32x2 helpers ----------------
__device__ __forceinline__ ull pack2(float lo, float hi) {
    ull r; asm("mov.b64 %0, {%1, %2};" : "=l"(r) : "f"(lo), "f"(hi)); return r;
}
__device__ __forceinline__ void unpack2(ull p, float& lo, float& hi) {
    asm("mov.b64 {%0, %1}, %2;" : "=f"(lo), "=f"(hi) : "l"(p));
}
__device__ __forceinline__ ull fma2(ull a, ull b, ull c) {
    ull r; asm("fma.rn.f32x2 %0, %1, %2, %3;" : "=l"(r) : "l"(a), "l"(b), "l"(c)); return r;
}
__device__ __forceinline__ ull mul2(ull a, ull b) {
    ull r; asm("mul.rn.f32x2 %0, %1, %2;" : "=l"(r) : "l"(a), "l"(b)); return r;
}
__device__ __forceinline__ ull add2(ull a, ull b) {
    ull r; asm("add.rn.f32x2 %0, %1, %2;" : "=l"(r) : "l"(a), "l"(b)); return r;
}
// packed relu(fp32x2) -> half2 bits
__device__ __forceinline__ unsigned relu_h2(ull e, __half2 hz) {
    float lo, hi;
    unpack2(e, lo, hi);
    __half2 h = __hmax2(__floats2half2_rn(lo, hi), hz);
    return *reinterpret_cast<unsigned*>(&h);
}

// ---------------------------------------------------------------------------
// Kernel 1: logits, with the LSTM gate computation FUSED in (blocks 0-31
// compute 4 hx values each, then everyone spins on g_cnt before the epilogue
// constants are staged). Warp-autonomous 32n x 128h tiles; embedding fused
// into the GEMM k-loop; tile loop barrier-free.
// ---------------------------------------------------------------------------
#define AH_STRIDE 72
#define AS_OFF   0        // 128*72 half2 = 9216 float-slots
#define XS_OFF   9216     // 4 warps x 64 float4 = 1024 floats (2 tiles)
#define WPS_OFF  10240    // 64 k2 x 4 ull = 512 floats
#define BPS_OFF  10752    // 64 ull = 128 floats
#define HXS_OFF  10880    // 128
#define VPS_OFF  11008    // 128
#define SM_FLOATS 11136   // 44.5 KB/CTA, x2 = 89 KB

__global__ __launch_bounds__(128, 2)
void k_logits(const float* __restrict__ nf, const float* __restrict__ Wemb,
              const float* __restrict__ bemb, const float* __restrict__ Wattn,
              const float* __restrict__ vparam, const float* __restrict__ Wih,
              const float* __restrict__ bih, const float* __restrict__ bhh,
              const float* __restrict__ q, float* __restrict__ out) {
    extern __shared__ float sm[];
    __half2* as2 = (__half2*)sm;              // [128][72]
    ull* wps     = (ull*)(sm + WPS_OFF);      // [64][4]
    ull* bps     = (ull*)(sm + BPS_OFF);      // [64]
    float* hxs   = sm + HXS_OFF;
    float* vps   = sm + VPS_OFF;

    int t = threadIdx.x;
    int lane = t & 31, w = t >> 5;
    int g = lane >> 2, tc = lane & 3;

    float4* xsw = (float4*)(sm + XS_OFF) + w * 64;

    // ---- gate phase: blocks 0-31, one warp per h (f-gate dead: f*c0 = 0) ----
    if (blockIdx.x < 32) {
        int h = blockIdx.x * 4 + w;
        float4 qv = __ldg((const float4*)q + lane);
        float a0, a1, a2;
        {
            float4 wv = __ldg((const float4*)(Wih + h * 128) + lane);
            a0 = wv.x * qv.x + wv.y * qv.y + wv.z * qv.z + wv.w * qv.w;
        }
        {
            float4 wv = __ldg((const float4*)(Wih + (256 + h) * 128) + lane);
            a1 = wv.x * qv.x + wv.y * qv.y + wv.z * qv.z + wv.w * qv.w;
        }
        {
            float4 wv = __ldg((const float4*)(Wih + (384 + h) * 128) + lane);
            a2 = wv.x * qv.x + wv.y * qv.y + wv.z * qv.z + wv.w * qv.w;
        }
        #pragma unroll
        for (int o = 16; o > 0; o >>= 1) {
            a0 += __shfl_xor_sync(0xffffffff, a0, o);
            a1 += __shfl_xor_sync(0xffffffff, a1, o);
            a2 += __shfl_xor_sync(0xffffffff, a2, o);
        }
        if (lane == 0) {
            float ig = a0 + bih[h] + bhh[h];
            float gg = a1 + bih[256 + h] + bhh[256 + h];
            float og = a2 + bih[384 + h] + bhh[384 + h];
            float si = 1.f / (1.f + __expf(-ig));
            float so = 1.f / (1.f + __expf(-og));
            float cx = si * tanh_fast(gg);
            g_hx[h] = so * tanh_fast(cx);
            __threadfence();
            atomicAdd(&g_cnt, 1);
        }
    }

    // ---- staging (overlaps the gate phase happening in blocks 0-31) ----
    for (int i = t * 4; i < 16384; i += 512) {
        float4 wv = *(const float4*)(Wattn + i);
        int h = i >> 7, k = i & 127;
        int k2 = k >> 1;
        int kb8 = k2 & ~7, j = k2 & 7;       // j in {0,2,4,6}
        int c1 = kb8 + ((j < 4) ? 2 * j : 2 * j - 7);
        as2[h * AH_STRIDE + c1]     = __floats2half2_rn(wv.x, wv.y);
        as2[h * AH_STRIDE + c1 + 2] = __floats2half2_rn(wv.z, wv.w);
    }
    if (t < 64) {
        int k2 = t;
        #pragma unroll
        for (int f = 0; f < 4; f++)
            wps[k2 * 4 + f] = pack2(Wemb[(2 * k2) * 4 + f],
                                    Wemb[(2 * k2 + 1) * 4 + f]);
        bps[k2] = pack2(bemb[2 * k2], bemb[2 * k2 + 1]);
    }
    vps[t] = vparam[t];

    // hoist BOTH tiles' node features (tiles gw and gw+1024)
    int gw = blockIdx.x * 4 + w;       // global warp id: 0..1023
    xsw[lane]      = __ldg((const float4*)nf + (gw * 32 + lane));
    xsw[32 + lane] = __ldg((const float4*)nf + ((gw + 1024) * 32 + lane));

    // ---- wait for all 128 gate warps, then stage hx ----
    if (t == 0) {
        volatile int* c = &g_cnt;
        while (*c < 128) { }
    }
    __syncthreads();
    __threadfence();            // acquire: g_hx writes visible
    hxs[t] = g_hx[t];
    __syncthreads();            // hxs ready

    const ull C3 = pack2(-0.3333333333f, -0.3333333333f);
    const ull C5 = pack2(0.1333333333f, 0.1333333333f);
    const ull C7 = pack2(-0.0539682540f, -0.0539682540f);
    const __half2 hzero = __floats2half2_rn(0.f, 0.f);

    #pragma unroll
    for (int it = 0; it < 2; it++) {
        int base = (gw + it * 1024) * 32;

        // lane's 4 nodes, packed
        ull xp[4][4];
        #pragma unroll
        for (int ni = 0; ni < 4; ni++) {
            float4 x = xsw[it * 32 + ni * 8 + g];
            xp[ni][0] = pack2(x.x, x.x);
            xp[ni][1] = pack2(x.y, x.y);
            xp[ni][2] = pack2(x.z, x.z);
            xp[ni][3] = pack2(x.w, x.w);
        }

        // ---- fused embed + fp16 GEMM: warp tile 128h x 32n ----
        float accr[8][4][4];
        #pragma unroll
        for (int mi = 0; mi < 8; mi++)
            #pragma unroll
            for (int ni = 0; ni < 4; ni++)
                #pragma unroll
                for (int j = 0; j < 4; j++) accr[mi][ni][j] = 0.f;

        #pragma unroll
        for (int kt = 0; kt < 8; kt++) {
            int k2a = kt * 8 + tc;
            int k2b = k2a + 4;
            ull wa0 = wps[k2a * 4], wa1 = wps[k2a * 4 + 1];
            ull wa2 = wps[k2a * 4 + 2], wa3 = wps[k2a * 4 + 3];
            ull ba = bps[k2a];
            ull wb0 = wps[k2b * 4], wb1 = wps[k2b * 4 + 1];
            ull wb2 = wps[k2b * 4 + 2], wb3 = wps[k2b * 4 + 3];
            ull bb = bps[k2b];

            uint2 bfr[4];
            #pragma unroll
            for (int ni = 0; ni < 4; ni++) {
                ull ea = ba;
                ea = fma2(xp[ni][0], wa0, ea);
                ea = fma2(xp[ni][1], wa1, ea);
                ea = fma2(xp[ni][2], wa2, ea);
                ea = fma2(xp[ni][3], wa3, ea);
                ull eb = bb;
                eb = fma2(xp[ni][0], wb0, eb);
                eb = fma2(xp[ni][1], wb1, eb);
                eb = fma2(xp[ni][2], wb2, eb);
                eb = fma2(xp[ni][3], wb3, eb);
                bfr[ni].x = relu_h2(ea, hzero);
                bfr[ni].y = relu_h2(eb, hzero);
            }

            int cb = kt * 8 + 2 * tc;
            #pragma unroll
            for (int mi = 0; mi < 8; mi++) {
                int r = mi * 16 + g;
                uint2 alo = *(const uint2*)(as2 + r * AH_STRIDE + cb);
                uint2 ahi = *(const uint2*)(as2 + (r + 8) * AH_STRIDE + cb);
                #pragma unroll
                for (int ni = 0; ni < 4; ni++) {
                    asm volatile(
                        "mma.sync.aligned.m16n8k16.row.col.f32.f16.f16.f32 "
                        "{%0,%1,%2,%3}, {%4,%5,%6,%7}, {%8,%9}, {%0,%1,%2,%3};"
                        : "+f"(accr[mi][ni][0]), "+f"(accr[mi][ni][1]),
                          "+f"(accr[mi][ni][2]), "+f"(accr[mi][ni][3])
                        : "r"(alo.x), "r"(ahi.x), "r"(alo.y), "r"(ahi.y),
                          "r"(bfr[ni].x), "r"(bfr[ni].y));
                }
            }
        }

        // ---- epilogue: v-weighted tanh, h-sum fully warp-internal ----
        ull s2[4];
        #pragma unroll
        for (int ni = 0; ni < 4; ni++) s2[ni] = pack2(0.f, 0.f);
        #pragma unroll
        for (int mi = 0; mi < 8; mi++) {
            int h0 = mi * 16 + g;
            ull hxa = pack2(hxs[h0], hxs[h0]);
            ull hxb = pack2(hxs[h0 + 8], hxs[h0 + 8]);
            ull va  = pack2(vps[h0], vps[h0]);
            ull vb  = pack2(vps[h0 + 8], vps[h0 + 8]);
            #pragma unroll
            for (int ni = 0; ni < 4; ni++) {
                ull ya = add2(pack2(accr[mi][ni][0], accr[mi][ni][1]), hxa);
                ull yb = add2(pack2(accr[mi][ni][2], accr[mi][ni][3]), hxb);
                if (mi < 4) {
                    float l0, l1;
                    unpack2(ya, l0, l1);
                    s2[ni] = fma2(va, pack2(tanh_fast(l0), tanh_fast(l1)), s2[ni]);
                    unpack2(yb, l0, l1);
                    s2[ni] = fma2(vb, pack2(tanh_fast(l0), tanh_fast(l1)), s2[ni]);
                } else {
                    ull ua = mul2(ya, ya);
                    ull qa = fma2(ua, C7, C5);
                    qa = fma2(ua, qa, C3);
                    ull ta = fma2(mul2(ya, ua), qa, ya);
                    s2[ni] = fma2(va, ta, s2[ni]);

                    ull ub = mul2(yb, yb);
                    ull qb = fma2(ub, C7, C5);
                    qb = fma2(ub, qb, C3);
                    ull tb = fma2(mul2(yb, ub), qb, yb);
                    s2[ni] = fma2(vb, tb, s2[ni]);
                }
            }
        }

        // reduce over g (lane bits 2..4)
        float pl[4][2];
        #pragma unroll
        for (int ni = 0; ni < 4; ni++) unpack2(s2[ni], pl[ni][0], pl[ni][1]);
        #pragma unroll
        for (int off = 4; off < 32; off <<= 1)
            #pragma unroll
            for (int ni = 0; ni < 4; ni++)
                #pragma unroll
                for (int j = 0; j < 2; j++)
                    pl[ni][j] += __shfl_xor_sync(0xffffffff, pl[ni][j], off);

        if (g == 0) {
            #pragma unroll
            for (int ni = 0; ni < 4; ni++)
                ((float2*)(out + base))[ni * 4 + tc] =
                    make_float2(pl[ni][0], pl[ni][1]);
        }
    }
}

// ---------------------------------------------------------------------------
// Kernel 2: softmax over N=1024 per batch (blocks 0..63) + v output and
// g_cnt reset (block 64).
// ---------------------------------------------------------------------------
__global__ void k_softmax(const float* __restrict__ Wval,
                          const float* __restrict__ bval,
                          float* __restrict__ out) {
    __shared__ float wred[8];
    __shared__ float bcast[2];
    int b = blockIdx.x;
    int t = threadIdx.x;
    int lane = t & 31, wid = t >> 5;

    if (b == 64) {
        if (t == 0) g_cnt = 0;   // reset for next graph replay
        if (wid == 0) {
            float s = g_hx[lane] * Wval[lane]
                    + g_hx[32 + lane] * Wval[32 + lane]
                    + g_hx[64 + lane] * Wval[64 + lane]
                    + g_hx[96 + lane] * Wval[96 + lane];
            #pragma unroll
            for (int o = 16; o > 0; o >>= 1)
                s += __shfl_xor_sync(0xffffffff, s, o);
            float v = s + bval[0];
            out[BN + lane] = v;
            out[BN + 32 + lane] = v;
        }
        return;
    }

    float* row = out + b * 1024;
    float4 x = ((const float4*)row)[t];
    float m = fmaxf(fmaxf(x.x, x.y), fmaxf(x.z, x.w));
    #pragma unroll
    for (int o = 16; o > 0; o >>= 1)
        m = fmaxf(m, __shfl_xor_sync(0xffffffff, m, o));
    if (lane == 0) wred[wid] = m;
    __syncthreads();
    if (wid == 0) {
        float mm = wred[lane & 7];
        #pragma unroll
        for (int o = 4; o > 0; o >>= 1)
            mm = fmaxf(mm, __shfl_xor_sync(0xffffffff, mm, o));
        if (lane == 0) bcast[0] = mm;
    }
    __syncthreads();
    float M = bcast[0];
    float e0 = __expf(x.x - M);
    float e1 = __expf(x.y - M);
    float e2 = __expf(x.z - M);
    float e3 = __expf(x.w - M);
    float s = e0 + e1 + e2 + e3;
    #pragma unroll
    for (int o = 16; o > 0; o >>= 1)
        s += __shfl_xor_sync(0xffffffff, s, o);
    if (lane == 0) wred[wid] = s;
    __syncthreads();
    if (wid == 0) {
        float ss = wred[lane & 7];
        #pragma unroll
        for (int o = 4; o > 0; o >>= 1)
            ss += __shfl_xor_sync(0xffffffff, ss, o);
        if (lane == 0) bcast[1] = ss;
    }
    __syncthreads();
    float inv = 1.f / bcast[1];
    float4 r;
    r.x = e0 * inv; r.y = e1 * inv; r.z = e2 * inv; r.w = e3 * inv;
    ((float4*)row)[t] = r;
}

// ---------------------------------------------------------------------------
extern "C" void kernel_launch(void* const* d_in, const int* in_sizes, int n_in,
                              void* d_out, int out_size) {
    const float* nf     = (const float*)d_in[0];
    const float* Wemb   = (const float*)d_in[2];
    const float* bemb   = (const float*)d_in[3];
    const float* Wih    = (const float*)d_in[4];
    const float* bih    = (const float*)d_in[5];
    const float* bhh    = (const float*)d_in[7];
    const float* query  = (const float*)d_in[8];
    const float* Wattn  = (const float*)d_in[9];
    const float* vparam = (const float*)d_in[10];
    const float* Wval   = (const float*)d_in[11];
    const float* bval   = (const float*)d_in[12];
    float* out = (float*)d_out;

    static int smem_set = 0;
    const int smem_bytes = SM_FLOATS * 4;
    if (!smem_set) {
        cudaFuncSetAttribute(k_logits, cudaFuncAttributeMaxDynamicSharedMemorySize,
                             smem_bytes);
        smem_set = 1;
    }

    k_logits<<<GRID_LOGITS, 128, smem_bytes>>>(nf, Wemb, bemb, Wattn, vparam,
                                               Wih, bih, bhh, query, out);
    k_softmax<<<65, 256>>>(Wval, bval, out);
}